// round 17
// baseline (speedup 1.0000x reference)
#include <cuda_runtime.h>
#include <cstdint>

#define S_DIM 16
#define M_DIM 768
#define N_DIM 1024
#define ROWS_PER_BLK 2
#define GROUPS_PER_IMG (M_DIM / ROWS_PER_BLK)      // 384
#define NGROUPS (S_DIM * GROUPS_PER_IMG)           // 6144
#define GRID 760                                   // 152 SMs x 5 blocks
#define LPAD 4
#define RPAD 4
#define RSTRIDE (LPAD + N_DIM + RPAD)              // 1032 floats = 4128 B
#define ROW_BYTES (N_DIM * 4)                      // 4096
#define RL_OFF (ROWS_PER_BLK * N_DIM)              // 2048 floats into a buffer
#define BUF_FLOATS (RL_OFF + 3 * RSTRIDE)          // 5144 floats = 20576 B
#define VEC_PER_ROW (RSTRIDE / 4)                  // 258
#define INVALID_VAL 100.0f

__device__ int g_ctr;

__global__ void reset_ctr_kernel() { g_ctr = 0; }

__device__ __forceinline__ uint32_t smem_u32(const void* p) {
    return (uint32_t)__cvta_generic_to_shared(p);
}

__global__ __launch_bounds__(256, 5) void lr_distance_kernel(
    const float* __restrict__ lr,
    const float* __restrict__ rl,
    float* __restrict__ out)
{
    // Two buffers, each: [lr row0 | lr row1 | rl row0 | rl row1 | rl row2]
    // Blend is in-place (row0 <- lerp(row0,row1), row2 <- lerp(row1,row2));
    // per-column same-thread read->write, row1 read-only => no blend barrier.
    // Invalid-lane gathers (idx down to -61) land in this block's lr region:
    // memory-safe garbage, always overwritten with INVALID_VAL.
    __shared__ __align__(16) float sm[2][BUF_FLOATS];   // 41152 B
    __shared__ __align__(8)  uint64_t mbar[2];
    __shared__ int g_slot[2];

    const int tid = threadIdx.x;

    // thread-0 helper: issue all TMA rows of group g into buffer b
    auto issue = [&](int g, int b) {
        int s     = g / GROUPS_PER_IMG;
        int grp   = g - s * GROUPS_PER_IMG;
        int ybase = grp * ROWS_PER_BLK;
        int g0    = ybase - (ybase < (M_DIM / 2) ? 1 : 0);
        int sbase = s * (M_DIM * N_DIM);
        int nrl   = 3 - (grp == 0) - (grp == GROUPS_PER_IMG - 1);
        uint32_t bar = smem_u32(&mbar[b]);
        asm volatile("mbarrier.arrive.expect_tx.shared.b64 _, [%0], %1;"
                     :: "r"(bar), "r"((ROWS_PER_BLK + nrl) * ROW_BYTES) : "memory");
        #pragma unroll
        for (int r = 0; r < ROWS_PER_BLK; r++) {
            uint32_t dst = smem_u32(&sm[b][r * N_DIM]);
            const float* src = lr + sbase + (ybase + r) * N_DIM;
            asm volatile(
                "cp.async.bulk.shared::cta.global.mbarrier::complete_tx::bytes "
                "[%0], [%1], %2, [%3];"
                :: "r"(dst), "l"(src), "r"(ROW_BYTES), "r"(bar) : "memory");
        }
        #pragma unroll
        for (int r = 0; r < 3; r++) {
            int gr = g0 + r;
            if (gr >= 0 && gr < M_DIM) {
                uint32_t dst = smem_u32(&sm[b][RL_OFF + r * RSTRIDE + LPAD]);
                const float* src = rl + sbase + gr * N_DIM;
                asm volatile(
                    "cp.async.bulk.shared::cta.global.mbarrier::complete_tx::bytes "
                    "[%0], [%1], %2, [%3];"
                    :: "r"(dst), "l"(src), "r"(ROW_BYTES), "r"(bar) : "memory");
            }
        }
    };

    // ── Startup: init barriers, fetch + issue first two groups ──
    if (tid == 0) {
        asm volatile("mbarrier.init.shared.b64 [%0], %1;"
                     :: "r"(smem_u32(&mbar[0])), "r"(1) : "memory");
        asm volatile("mbarrier.init.shared.b64 [%0], %1;"
                     :: "r"(smem_u32(&mbar[1])), "r"(1) : "memory");
        asm volatile("fence.proxy.async.shared::cta;" ::: "memory");
        int ga = atomicAdd(&g_ctr, 1);
        g_slot[0] = ga;
        if (ga < NGROUPS) issue(ga, 0);
        int gb = atomicAdd(&g_ctr, 1);
        g_slot[1] = gb;
        if (gb < NGROUPS) issue(gb, 1);
    }
    // Zero pads of all staged rows in both buffers (48 entries, once; blend
    // rewrites them with lerp(0,0)=0 every iteration, so they stay zero).
    if (tid < 2 * 3 * (LPAD + RPAD)) {
        int b = tid / 24, v = tid % 24;
        int r = v / (LPAD + RPAD), p = v % (LPAD + RPAD);
        int idx = (p < LPAD) ? p : (N_DIM + p);
        sm[b][RL_OFF + r * RSTRIDE + idx] = 0.0f;
    }
    __syncthreads();   // publishes inits, g_slot, pad zeros

    const float RCP_SCALE = 2.0f / 1023.0f;
    uint32_t phase0 = 0, phase1 = 0;

    for (int it = 0; ; ++it) {
        const int b = it & 1;
        const int g = g_slot[b];
        if (g >= NGROUPS) break;     // later slot was fetched later => also invalid

        const int s     = g / GROUPS_PER_IMG;
        const int grp   = g - s * GROUPS_PER_IMG;
        const int ybase = grp * ROWS_PER_BLK;
        const int sbase = s * (M_DIM * N_DIM);
        const bool oob_top = (grp == 0);                    // staged row0 is y=-1
        const bool oob_bot = (grp == GROUPS_PER_IMG - 1);   // staged row2 is y=768

        // Wait for this buffer's TMA batch (prefetched >=1 iteration ago)
        {
            uint32_t bar = smem_u32(&mbar[b]);
            uint32_t ph  = b ? phase1 : phase0;
            uint32_t done;
            do {
                asm volatile(
                    "{\n\t.reg .pred p;\n\t"
                    "mbarrier.try_wait.parity.acquire.cta.shared::cta.b64 p, [%1], %2;\n\t"
                    "selp.b32 %0, 1, 0, p;\n\t}"
                    : "=r"(done) : "r"(bar), "r"(ph) : "memory");
            } while (!done);
            if (b) phase1 ^= 1; else phase0 ^= 1;
        }

        // Vertical weights (blend row r reads staged rows r, r+1 — all groups)
        float wy1v[ROWS_PER_BLK];
        #pragma unroll
        for (int r = 0; r < ROWS_PER_BLK; r++) {
            const int y = ybase + r;
            float yl  = 2.0f * (float)y / (float)(M_DIM - 1) - 1.0f;
            float iy  = ((yl + 1.0f) * (float)M_DIM - 1.0f) * 0.5f;
            wy1v[r] = iy - floorf(iy);
        }

        float* __restrict__ buf = sm[b];

        // In-place blend, no barrier; OOB rows become zeros via block-uniform selects
        {
            const float4* __restrict__ r0v = reinterpret_cast<const float4*>(buf + RL_OFF);
            const float4* __restrict__ r1v = reinterpret_cast<const float4*>(buf + RL_OFF + RSTRIDE);
            const float4* __restrict__ r2v = reinterpret_cast<const float4*>(buf + RL_OFF + 2 * RSTRIDE);
            float4* __restrict__ d0 = reinterpret_cast<float4*>(buf + RL_OFF);
            float4* __restrict__ d2 = reinterpret_cast<float4*>(buf + RL_OFF + 2 * RSTRIDE);
            const float4 z4 = make_float4(0.f, 0.f, 0.f, 0.f);
            float w0 = wy1v[0], w1 = wy1v[1];

            for (int c = tid; c < VEC_PER_ROW; c += 256) {
                float4 v1 = r1v[c];
                float4 v0 = oob_top ? z4 : r0v[c];
                float4 v2 = oob_bot ? z4 : r2v[c];
                float4 o0, o2;
                o0.x = fmaf(w0, v1.x - v0.x, v0.x);
                o0.y = fmaf(w0, v1.y - v0.y, v0.y);
                o0.z = fmaf(w0, v1.z - v0.z, v0.z);
                o0.w = fmaf(w0, v1.w - v0.w, v0.w);
                o2.x = fmaf(w1, v2.x - v1.x, v1.x);
                o2.y = fmaf(w1, v2.y - v1.y, v1.y);
                o2.z = fmaf(w1, v2.z - v1.z, v1.z);
                o2.w = fmaf(w1, v2.w - v1.w, v1.w);
                d0[c] = o0;
                d2[c] = o2;
            }
        }
        __syncthreads();   // blends visible to all

        // Gather: lr from smem (coalesced) + 2 random scalar taps per element
        {
            const int   xs  = tid * 4;
            const float xlb = (float)xs;

            #pragma unroll
            for (int r = 0; r < ROWS_PER_BLK; r++) {
                const int y = ybase + r;
                const float* __restrict__ rowb = buf + RL_OFF + (2 * r) * RSTRIDE;

                float4 dv = *reinterpret_cast<const float4*>(buf + r * N_DIM + xs);
                float dd[4] = {dv.x, dv.y, dv.z, dv.w};
                float res[4];

                #pragma unroll
                for (int j = 0; j < 4; j++) {
                    float d  = dd[j];
                    float xr = (xlb + (float)j) - d;

                    float t   = fmaf(xr, RCP_SCALE, -1.0f);
                    float ix  = fmaf(t, 512.0f, 511.5f);
                    float x0f = floorf(ix);
                    float wx1 = ix - x0f;
                    int   idx = (int)x0f + LPAD;   // valid: [3,1027]; negatives only
                                                   // for invalid lanes (safe garbage)
                    float b0 = rowb[idx];
                    float b1 = rowb[idx + 1];
                    float warped = fmaf(wx1, b1 - b0, b0);

                    float dist = fabsf(d + warped);
                    res[j] = (xr < 0.0f) ? INVALID_VAL : dist;   // d>=0 => no right OOB
                }

                *reinterpret_cast<float4*>(out + sbase + y * N_DIM + xs) =
                    make_float4(res[0], res[1], res[2], res[3]);
            }
        }
        __syncthreads();   // buffer b fully consumed -> safe to refill

        // Refill this buffer with the next group (consumed at iteration it+2;
        // the two barriers of iteration it+1 publish g_slot[b] before that read)
        if (tid == 0) {
            int gn = atomicAdd(&g_ctr, 1);
            g_slot[b] = gn;
            if (gn < NGROUPS) issue(gn, b);
        }
    }
}

extern "C" void kernel_launch(void* const* d_in, const int* in_sizes, int n_in,
                              void* d_out, int out_size)
{
    const float* lr = (const float*)d_in[0];
    const float* rl = (const float*)d_in[1];
    float* out = (float*)d_out;

    reset_ctr_kernel<<<1, 1>>>();
    lr_distance_kernel<<<GRID, 256>>>(lr, rl, out);
}